// round 8
// baseline (speedup 1.0000x reference)
#include <cuda_runtime.h>
#include <cuda_bf16.h>
#include <cstdint>

#define B_   8
#define C_   256
#define H_   96
#define W_   96
#define HW_  (H_*W_)          // 9216
#define G_   4
#define CG_  64
#define HO_  192
#define WO_  192
#define HOWO_ (HO_*WO_)
#define NOUT_ 32

// Scratch coords (ix, iy) per output pixel, layout [n][oy][ox]
__device__ __align__(16) float2 g_coords[B_ * G_ * HO_ * WO_];   // 9.4 MB

// ---------------------------------------------------------------------------
// Kernel 1: offset head GEMV (R1 shape: 192 thr = 96x2, grid 48x8, unroll 2).
// ---------------------------------------------------------------------------
__global__ __launch_bounds__(192) void dysample_offset_kernel(
    const float* __restrict__ x,
    const float* __restrict__ w_off,
    const float* __restrict__ b_off)
{
    __shared__ __align__(16) float w_sh[NOUT_ * C_];   // 32 KB, natural [o][c]
    __shared__ float b_sh[NOUT_];

    const int tid = threadIdx.y * 96 + threadIdx.x;
    for (int i = tid; i < NOUT_ * C_; i += 192) w_sh[i] = w_off[i];
    if (tid < NOUT_) b_sh[tid] = b_off[tid];
    __syncthreads();

    const int b = blockIdx.y;
    const int h = blockIdx.x * 2 + threadIdx.y;
    const int w = threadIdx.x;

    const float* xp = x + (size_t)b * C_ * HW_ + h * W_ + w;

    float acc[NOUT_];
#pragma unroll
    for (int o = 0; o < NOUT_; o++) acc[o] = 0.f;

#pragma unroll 2
    for (int cb = 0; cb < C_; cb += 4) {
        const float xv0 = xp[(cb + 0) * HW_];
        const float xv1 = xp[(cb + 1) * HW_];
        const float xv2 = xp[(cb + 2) * HW_];
        const float xv3 = xp[(cb + 3) * HW_];
#pragma unroll
        for (int o = 0; o < NOUT_; o++) {
            const float4 wv = *(const float4*)&w_sh[o * C_ + cb];
            float t = acc[o];
            t = fmaf(xv0, wv.x, t);
            t = fmaf(xv1, wv.y, t);
            t = fmaf(xv2, wv.z, t);
            t = fmaf(xv3, wv.w, t);
            acc[o] = t;
        }
    }

    const float wf = (float)w;
    const float hf = (float)h;
#pragma unroll
    for (int gi = 0; gi < G_; gi++) {
#pragma unroll
        for (int sy = 0; sy < 2; sy++) {
#pragma unroll
            for (int sx = 0; sx < 2; sx++) {
                const int idx = gi * 4 + sy * 2 + sx;
                float ix = wf + (acc[idx]      + b_sh[idx])      * 0.25f;
                float iy = hf + (acc[16 + idx] + b_sh[16 + idx]) * 0.25f;
                ix = fminf(fmaxf(ix, 0.f), (float)(W_ - 1));
                iy = fminf(fmaxf(iy, 0.f), (float)(H_ - 1));
                const int n  = b * G_ + gi;
                const int oy = 2 * h + sy;
                const int ox = 2 * w + sx;
                g_coords[((size_t)n * HO_ + oy) * WO_ + ox] = make_float2(ix, iy);
            }
        }
    }
}

// ---------------------------------------------------------------------------
// Kernel 2: direct bilinear gather, 2 output pixels per thread (ox = 2q, 2q+1).
// One float4 coord load, 8 precomputed tap pointers, STG.64 output.
// 64 channels as outer-16 x inner-4 (inner addresses are immediate offsets).
// ---------------------------------------------------------------------------
__global__ __launch_bounds__(256) void dysample_sample_kernel(
    const float* __restrict__ x,
    float* __restrict__ out)
{
    const int t   = blockIdx.x * 256 + threadIdx.x;   // pair id, 0..589823
    const int n   = t / (HO_ * 96);
    const int rem = t % (HO_ * 96);
    const int oy  = rem / 96;
    const int q   = rem % 96;
    const int b   = n >> 2;
    const int gi  = n & 3;

    const float4 c2 = *(const float4*)&g_coords[((size_t)n * HO_ + oy) * WO_ + 2 * q];

    // Pixel A (ox = 2q)
    const float xA0f = floorf(c2.x), yA0f = floorf(c2.y);
    const int   xA0 = (int)xA0f,     yA0 = (int)yA0f;
    const float wxA = c2.x - xA0f,   wyA = c2.y - yA0f;
    const int   xA1 = min(xA0 + 1, W_ - 1);
    const int   yA1 = min(yA0 + 1, H_ - 1);
    const float wA00 = (1.f - wyA) * (1.f - wxA);
    const float wA01 = (1.f - wyA) * wxA;
    const float wA10 = wyA * (1.f - wxA);
    const float wA11 = wyA * wxA;

    // Pixel B (ox = 2q+1)
    const float xB0f = floorf(c2.z), yB0f = floorf(c2.w);
    const int   xB0 = (int)xB0f,     yB0 = (int)yB0f;
    const float wxB = c2.z - xB0f,   wyB = c2.w - yB0f;
    const int   xB1 = min(xB0 + 1, W_ - 1);
    const int   yB1 = min(yB0 + 1, H_ - 1);
    const float wB00 = (1.f - wyB) * (1.f - wxB);
    const float wB01 = (1.f - wyB) * wxB;
    const float wB10 = wyB * (1.f - wxB);
    const float wB11 = wyB * wxB;

    const float* __restrict__ base = x + (size_t)(b * C_ + gi * CG_) * HW_;
    const float* a00 = base + yA0 * W_ + xA0;
    const float* a01 = base + yA0 * W_ + xA1;
    const float* a10 = base + yA1 * W_ + xA0;
    const float* a11 = base + yA1 * W_ + xA1;
    const float* b00 = base + yB0 * W_ + xB0;
    const float* b01 = base + yB0 * W_ + xB1;
    const float* b10 = base + yB1 * W_ + xB0;
    const float* b11 = base + yB1 * W_ + xB1;

    float* op = out + (size_t)(b * C_ + gi * CG_) * HOWO_ + oy * WO_ + 2 * q;

#pragma unroll 1
    for (int cb = 0; cb < CG_; cb += 4) {
#pragma unroll
        for (int cc = 0; cc < 4; cc++) {
            const int o = cc * HW_;           // SASS immediate
            float vA = wA00 * __ldg(a00 + o);
            float vB = wB00 * __ldg(b00 + o);
            vA = fmaf(wA01, __ldg(a01 + o), vA);
            vB = fmaf(wB01, __ldg(b01 + o), vB);
            vA = fmaf(wA10, __ldg(a10 + o), vA);
            vB = fmaf(wB10, __ldg(b10 + o), vB);
            vA = fmaf(wA11, __ldg(a11 + o), vA);
            vB = fmaf(wB11, __ldg(b11 + o), vB);
            *(float2*)(op + (size_t)cc * HOWO_) = make_float2(vA, vB);
        }
        a00 += 4 * HW_; a01 += 4 * HW_; a10 += 4 * HW_; a11 += 4 * HW_;
        b00 += 4 * HW_; b01 += 4 * HW_; b10 += 4 * HW_; b11 += 4 * HW_;
        op  += (size_t)4 * HOWO_;
    }
}

// ---------------------------------------------------------------------------
extern "C" void kernel_launch(void* const* d_in, const int* in_sizes, int n_in,
                              void* d_out, int out_size)
{
    const float* x     = (const float*)d_in[0];
    const float* w_off = (const float*)d_in[1];
    const float* b_off = (const float*)d_in[2];
    float* out = (float*)d_out;

    dysample_offset_kernel<<<dim3(48, B_), dim3(96, 2)>>>(x, w_off, b_off);
    dysample_sample_kernel<<<(B_ * G_ * HO_ * 96) / 256, 256>>>(x, out);
}